// round 16
// baseline (speedup 1.0000x reference)
#include <cuda_runtime.h>
#include <cuda_fp16.h>
#include <math.h>
#include <stdint.h>

#define H 128
#define OMEGA 30.0f
#define NVAC 16
#define NT 384          // 12 warps -> balanced 3 per SMSP
#define ROWS_PER_TILE 192
#define SB 148          // stats blocks == #SMs (co-resident guaranteed)

__device__ float g_psum[SB][3];
__device__ float g_pmax[SB];
__device__ unsigned int g_arrive;   // monotonic across graph replays
__device__ double g_huber;

// ---------------- helpers ----------------
__device__ __forceinline__ float wred_sum(float x){
    #pragma unroll
    for (int o = 16; o > 0; o >>= 1) x += __shfl_xor_sync(0xffffffffu, x, o);
    return x;
}
__device__ __forceinline__ float wred_max(float x){
    #pragma unroll
    for (int o = 16; o > 0; o >>= 1) x = fmaxf(x, __shfl_xor_sync(0xffffffffu, x, o));
    return x;
}
__device__ __forceinline__ float clipf(float x, float b){ return fminf(fmaxf(x, -b), b); }
__device__ __forceinline__ float huber1(float d){
    float a = fabsf(d);
    return (a < 1.0f) ? 0.5f * d * d : a - 0.5f;
}
__device__ __forceinline__ uint32_t smem_u32(const void* p){
    uint32_t a;
    asm("{ .reg .u64 t; cvta.to.shared.u64 t, %1; cvt.u32.u64 %0, t; }" : "=r"(a) : "l"(p));
    return a;
}

__device__ __forceinline__ uint32_t pack_f16(float e, float o){
    uint32_t h;
    asm("cvt.rn.f16x2.f32 %0, %1, %2;" : "=r"(h) : "f"(o), "f"(e));
    return h;
}
__device__ __forceinline__ uint32_t hmul2(uint32_t a, uint32_t b){
    uint32_t r;
    asm("mul.f16x2 %0, %1, %2;" : "=r"(r) : "r"(a), "r"(b));
    return r;
}

__device__ __forceinline__ void mma16816(float* c, const uint32_t* a, uint32_t b0, uint32_t b1){
    asm("mma.sync.aligned.m16n8k16.row.col.f32.f16.f16.f32 "
        "{%0,%1,%2,%3}, {%4,%5,%6,%7}, {%8,%9}, {%0,%1,%2,%3};"
        : "+f"(c[0]), "+f"(c[1]), "+f"(c[2]), "+f"(c[3])
        : "r"(a[0]), "r"(a[1]), "r"(a[2]), "r"(a[3]), "r"(b0), "r"(b1));
}
__device__ __forceinline__ void ldsm_x4(uint32_t &r0, uint32_t &r1, uint32_t &r2, uint32_t &r3, uint32_t addr){
    asm volatile("ldmatrix.sync.aligned.m8n8.x4.shared.b16 {%0,%1,%2,%3}, [%4];"
        : "=r"(r0), "=r"(r1), "=r"(r2), "=r"(r3) : "r"(addr));
}
__device__ __forceinline__ void ldsm_x4_t(uint32_t &r0, uint32_t &r1, uint32_t &r2, uint32_t &r3, uint32_t addr){
    asm volatile("ldmatrix.sync.aligned.m8n8.x4.trans.shared.b16 {%0,%1,%2,%3}, [%4];"
        : "=r"(r0), "=r"(r1), "=r"(r2), "=r"(r3) : "r"(addr));
}

// ---------------- smem layout (bytes) ----------------
#define OFF_W1HI 0          // 32768
#define OFF_W0Q  32768      // 128 * float4 = 2048
#define OFF_BW   34816      // 128 * float2 (b1, w2) = 1024
#define OFF_RED  35840      // 16 f
#define SM_MAIN  35968

// ---------------- fused stats kernel (1 launch, software barrier) ----------------
__global__ __launch_bounds__(256) void k_stats(const float* __restrict__ pos, int n){
    const int bid = blockIdx.x, tid = threadIdx.x;
    __shared__ float sred[8][3];
    __shared__ float smax[8];

    // phase 1: partial sums
    float sx=0.f, sy=0.f, sz=0.f;
    for (int i = bid*256 + tid; i < n; i += SB*256){
        sx += pos[3*i]; sy += pos[3*i+1]; sz += pos[3*i+2];
    }
    sx = wred_sum(sx); sy = wred_sum(sy); sz = wred_sum(sz);
    if ((tid & 31) == 0){ sred[tid>>5][0]=sx; sred[tid>>5][1]=sy; sred[tid>>5][2]=sz; }
    __syncthreads();
    if (tid == 0){
        float a=0.f,b=0.f,c=0.f;
        #pragma unroll
        for (int i2 = 0; i2 < 8; i2++){ a+=sred[i2][0]; b+=sred[i2][1]; c+=sred[i2][2]; }
        g_psum[bid][0]=a; g_psum[bid][1]=b; g_psum[bid][2]=c;
        if (bid == 0) g_huber = 0.0;
    }
    __threadfence();
    __syncthreads();

    // barrier: monotonic counter, replay-safe (advances exactly SB per replay)
    if (tid == 0){
        unsigned old = atomicAdd(&g_arrive, 1u);
        unsigned tgt = old - (old % (unsigned)SB) + (unsigned)SB;
        while ((int)(atomicAdd(&g_arrive, 0u) - tgt) < 0) { }
    }
    __syncthreads();
    __threadfence();

    // phase 2: center, then partial max of ||p-c||^2
    float c0=0.f, c1=0.f, c2=0.f;
    for (int j = 0; j < SB; j++){ c0+=g_psum[j][0]; c1+=g_psum[j][1]; c2+=g_psum[j][2]; }
    float inv_n = 1.0f/(float)n;
    c0*=inv_n; c1*=inv_n; c2*=inv_n;
    float m = 0.f;
    for (int i = bid*256 + tid; i < n; i += SB*256){
        float dx=pos[3*i]-c0, dy=pos[3*i+1]-c1, dz=pos[3*i+2]-c2;
        m = fmaxf(m, dx*dx+dy*dy+dz*dz);
    }
    m = wred_max(m);
    if ((tid & 31) == 0) smax[tid>>5] = m;
    __syncthreads();
    if (tid == 0){
        float mm = 0.f;
        #pragma unroll
        for (int i2 = 0; i2 < 8; i2++) mm = fmaxf(mm, smax[i2]);
        g_pmax[bid] = mm;
    }
}

__device__ __forceinline__ void get_center(int n, float &c0, float &c1, float &c2){
    float a=0.f,b=0.f,c=0.f;
    for (int j = 0; j < SB; j++){ a+=g_psum[j][0]; b+=g_psum[j][1]; c+=g_psum[j][2]; }
    float inv_n = 1.0f/(float)n;
    c0=a*inv_n; c1=b*inv_n; c2=c*inv_n;
}

__device__ __forceinline__ void calc_coord(const float* __restrict__ pos, const float* __restrict__ forces,
                                           int idx, int n, float cen0, float cen1, float cen2,
                                           float &cx, float &cy, float &cz,
                                           float &tx, float &ty, float &tz){
    cx = 0.f; cy = 0.f; cz = 0.f; tx = 0.f; ty = 0.f; tz = 0.f;
    if (idx < n){
        float px = pos[3*idx], py = pos[3*idx+1], pz = pos[3*idx+2];
        float fx = forces[3*idx], fy = forces[3*idx+1], fz = forces[3*idx+2];
        float dx = fx + 0.1f*(px - cen0);
        float dy = fy + 0.1f*(py - cen1);
        float dz = fz + 0.1f*(pz - cen2);
        float nrm = fmaxf(sqrtf(dx*dx + dy*dy + dz*dz), 1e-8f);
        float inv = 1.0f/nrm;
        cx = px + 0.01f*dx*inv; cy = py + 0.01f*dy*inv; cz = pz + 0.01f*dz*inv;
        tx = clipf(fx, 25.f); ty = clipf(fy, 25.f); tz = clipf(fz, 25.f);
    }
}

// ---------------- main mma.sync kernel (fp16, 12 warps, MMA epilogue) ----------------
__global__ __launch_bounds__(NT, 1)
void k_main_mma(const float* __restrict__ pos, const float* __restrict__ forces,
                const float* __restrict__ W0, const float* __restrict__ b0,
                const float* __restrict__ W1, const float* __restrict__ b1,
                const float* __restrict__ W2,
                float* __restrict__ out_grads, int n)
{
    extern __shared__ char smc[];
    const uint32_t sb = smem_u32(smc);
    const int tid = threadIdx.x;

    float4*  w0qv = (float4*)(smc + OFF_W0Q);
    float2*  bwf  = (float2*)(smc + OFF_BW);
    float*   red  = (float*)(smc + OFF_RED);

    // one-time: W1 -> fp16, 16B-chunk XOR swizzle per row
    for (int i = tid; i < H*H; i += NT){
        int j = i >> 7, k = i & 127;
        __half hb = __float2half_rn(W1[i]);
        uint32_t off = (uint32_t)(j*256 + (((k>>3) ^ (j&7))<<4) + (k&7)*2);
        *(unsigned short*)(smc + OFF_W1HI + off) = __half_as_ushort(hb);
    }
    for (int i = tid; i < H; i += NT){
        float4 q;
        q.x = OMEGA*W0[i]; q.y = OMEGA*W0[H+i]; q.z = OMEGA*W0[2*H+i]; q.w = OMEGA*b0[i];
        w0qv[i] = q;
        float2 bw; bw.x = b1[i]; bw.y = W2[i];
        bwf[i] = bw;
    }
    __syncthreads();

    float cen0, cen1, cen2;
    get_center(n, cen0, cen1, cen2);

    const int lane = tid & 31, w = tid >> 5;
    const int r = lane >> 2, cq = lane & 3;
    const int rowA = w*16 + r;            // rowB = rowA + 8
    const uint32_t laneHalf = (uint32_t)(lane >> 4);
    const uint32_t sxl      = (uint32_t)(lane & 7);
    const uint32_t trowB    = (uint32_t)(lane & 15) * 256;
    const uint32_t nrowB    = (uint32_t)(lane & 7) * 256;
    const uint32_t kpar     = (uint32_t)((lane >> 3) & 1);
    const uint32_t hiB = sb + OFF_W1HI;

    // ---- epilogue B fragments: W0 (raw, fp16). B[k=j][n=i]; n=r(0..7), rows>=3 zero
    uint32_t w0b[8][2];
    #pragma unroll
    for (int kk = 0; kk < 8; kk++){
        int k0 = kk*16 + 2*cq;
        float b00 = 0.f, b01 = 0.f, b10 = 0.f, b11 = 0.f;
        if (r < 3){
            b00 = W0[r*H + k0];   b01 = W0[r*H + k0 + 1];
            b10 = W0[r*H + k0 + 8]; b11 = W0[r*H + k0 + 9];
        }
        w0b[kk][0] = pack_f16(b00, b01);
        w0b[kk][1] = pack_f16(b10, b11);
    }

    const int ntiles = (n + ROWS_PER_TILE - 1) / ROWS_PER_TILE;
    float hub = 0.f;

    for (int tile = blockIdx.x; tile < ntiles; tile += gridDim.x){
        const int idxA = tile*ROWS_PER_TILE + rowA;
        const int idxB = idxA + 8;
        float cAx, cAy, cAz, cBx, cBy, cBz;
        float tAx, tAy, tAz, tBx, tBy, tBz;
        calc_coord(pos, forces, idxA, n, cen0, cen1, cen2, cAx, cAy, cAz, tAx, tAy, tAz);
        calc_coord(pos, forces, idxB, n, cen0, cen1, cen2, cBx, cBy, cBz, tBx, tBy, tBz);

        // ---- layer 0: sin(z0) -> fp16 A1 frags, cos(z0) packed f16 regs
        uint32_t a1h[8][4];
        uint32_t c0p[16][2];
        #pragma unroll
        for (int kt = 0; kt < 8; kt++){
            #pragma unroll
            for (int half = 0; half < 2; half++){
                int j0 = kt*16 + half*8 + 2*cq;
                float4 q0 = w0qv[j0], q1 = w0qv[j0+1];
                float zA0 = fmaf(cAx,q0.x, fmaf(cAy,q0.y, fmaf(cAz,q0.z, q0.w)));
                float zA1 = fmaf(cAx,q1.x, fmaf(cAy,q1.y, fmaf(cAz,q1.z, q1.w)));
                float zB0 = fmaf(cBx,q0.x, fmaf(cBy,q0.y, fmaf(cBz,q0.z, q0.w)));
                float zB1 = fmaf(cBx,q1.x, fmaf(cBy,q1.y, fmaf(cBz,q1.z, q1.w)));
                float sA0,cA0,sA1,cA1,sB0,cB0,sB1,cB1;
                __sincosf(zA0,&sA0,&cA0); __sincosf(zA1,&sA1,&cA1);
                __sincosf(zB0,&sB0,&cB0); __sincosf(zB1,&sB1,&cB1);
                int ntg = kt*2 + half;
                c0p[ntg][0] = pack_f16(cA0, cA1);
                c0p[ntg][1] = pack_f16(cB0, cB1);
                a1h[kt][half*2+0] = pack_f16(sA0, sA1);
                a1h[kt][half*2+1] = pack_f16(sB0, sB1);
            }
        }

        // ---- GEMM1 in 2 chunks of 8 n-tiles (8-wide MMA waves) + immediate cos -> a2h
        uint32_t a2h[8][4];
        #pragma unroll
        for (int ch = 0; ch < 2; ch++){
            float c1c[8][4];
            #pragma unroll
            for (int i = 0; i < 8; i++){ c1c[i][0]=0.f; c1c[i][1]=0.f; c1c[i][2]=0.f; c1c[i][3]=0.f; }
            #pragma unroll
            for (int kt = 0; kt < 8; kt++){
                uint32_t bb[4][4];
                #pragma unroll
                for (int ii = 0; ii < 4; ii++){
                    uint32_t cidxL = (uint32_t)(ch*8 + 2*ii) + laneHalf;
                    uint32_t boff = (uint32_t)kt*4096 + trowB + ((cidxL ^ sxl) << 4);
                    ldsm_x4_t(bb[ii][0], bb[ii][1], bb[ii][2], bb[ii][3], hiB + boff);
                }
                #pragma unroll
                for (int ii = 0; ii < 4; ii++) mma16816(c1c[2*ii+0], a1h[kt], bb[ii][0], bb[ii][1]);
                #pragma unroll
                for (int ii = 0; ii < 4; ii++) mma16816(c1c[2*ii+1], a1h[kt], bb[ii][2], bb[ii][3]);
            }
            #pragma unroll
            for (int t8 = 0; t8 < 8; t8++){
                int ntg = ch*8 + t8;
                int col0 = ntg*8 + 2*cq;
                float2 p0 = bwf[col0], p1 = bwf[col0+1];
                float u0 = __cosf(OMEGA*(c1c[t8][0] + p0.x)) * p0.y;
                float u1 = __cosf(OMEGA*(c1c[t8][1] + p1.x)) * p1.y;
                float u2 = __cosf(OMEGA*(c1c[t8][2] + p0.x)) * p0.y;
                float u3 = __cosf(OMEGA*(c1c[t8][3] + p1.x)) * p1.y;
                int kk = ntg >> 1, s2 = ntg & 1;
                a2h[kk][s2*2+0] = pack_f16(u0, u1);
                a2h[kk][s2*2+1] = pack_f16(u2, u3);
            }
        }

        // ---- GEMM2: v = U @ W1^T; full width, 8-wide waves
        float c2[16][4];
        #pragma unroll
        for (int i = 0; i < 16; i++){ c2[i][0]=0.f; c2[i][1]=0.f; c2[i][2]=0.f; c2[i][3]=0.f; }
        #pragma unroll
        for (int kk = 0; kk < 8; kk++){
            uint32_t bb[8][4];
            #pragma unroll
            for (int ii = 0; ii < 8; ii++){
                uint32_t nt2L = (uint32_t)(2*ii) + laneHalf;
                uint32_t kcc = ((uint32_t)(kk*2) + kpar) ^ sxl;
                uint32_t boff = nt2L*2048 + nrowB + (kcc << 4);
                ldsm_x4(bb[ii][0], bb[ii][1], bb[ii][2], bb[ii][3], hiB + boff);
            }
            #pragma unroll
            for (int ii = 0; ii < 8; ii++) mma16816(c2[2*ii+0], a2h[kk], bb[ii][0], bb[ii][1]);
            #pragma unroll
            for (int ii = 0; ii < 8; ii++) mma16816(c2[2*ii+1], a2h[kk], bb[ii][2], bb[ii][3]);
        }

        // ---- epilogue GEMM3: g = Omega^2 * (c0 .* v) @ W0^T  (N=3 used of 8)
        float c3[4] = {0.f, 0.f, 0.f, 0.f};
        #pragma unroll
        for (int kk = 0; kk < 8; kk++){
            int e = 2*kk;
            uint32_t af[4];
            af[0] = hmul2(c0p[e][0],   pack_f16(c2[e][0],   c2[e][1]));
            af[1] = hmul2(c0p[e][1],   pack_f16(c2[e][2],   c2[e][3]));
            af[2] = hmul2(c0p[e+1][0], pack_f16(c2[e+1][0], c2[e+1][1]));
            af[3] = hmul2(c0p[e+1][1], pack_f16(c2[e+1][2], c2[e+1][3]));
            mma16816(c3, af, w0b[kk][0], w0b[kk][1]);
        }
        float gzA = __shfl_down_sync(0xffffffffu, c3[0], 1);
        float gzB = __shfl_down_sync(0xffffffffu, c3[2], 1);
        if (cq == 0){
            const float O2 = OMEGA*OMEGA;
            if (idxA < n){
                float gx = clipf(O2*c3[0], 25.f), gy = clipf(O2*c3[1], 25.f), gz = clipf(O2*gzA, 25.f);
                out_grads[3*idxA] = gx; out_grads[3*idxA+1] = gy; out_grads[3*idxA+2] = gz;
                hub += huber1(gx - tAx) + huber1(gy - tAy) + huber1(gz - tAz);
            }
            if (idxB < n){
                float gx = clipf(O2*c3[2], 25.f), gy = clipf(O2*c3[3], 25.f), gz = clipf(O2*gzB, 25.f);
                out_grads[3*idxB] = gx; out_grads[3*idxB+1] = gy; out_grads[3*idxB+2] = gz;
                hub += huber1(gx - tBx) + huber1(gy - tBy) + huber1(gz - tBz);
            }
        }
    }

    hub = wred_sum(hub);
    __syncthreads();
    if (lane == 0) red[w] = hub;
    __syncthreads();
    if (tid == 0){
        double s = 0.0;
        #pragma unroll
        for (int i = 0; i < NT/32; i++) s += (double)red[i];
        atomicAdd(&g_huber, s);
    }
}

// -------- vacuum points + finalize --------
#define SM_VAC_FLOATS (16512 + 384 + 128 + 128 + 128 + 4*(NVAC*H) + 16 + 512)

__global__ __launch_bounds__(512) void k_vac(
    const float* __restrict__ W0, const float* __restrict__ b0,
    const float* __restrict__ W1, const float* __restrict__ b1,
    const float* __restrict__ W2, const float* __restrict__ b2,
    const float* __restrict__ alpha, const float* __restrict__ atg,
    float* __restrict__ out, int n)
{
    extern __shared__ float sm[];
    float* W1p = sm;
    float* W0s = sm + 16512;
    float* b0s = W0s + 384;
    float* b1s = b0s + 128;
    float* w2s = b1s + 128;
    float* s0s = w2s + 128;
    float* c0s = s0s + NVAC*H;
    float* s1s = c0s + NVAC*H;
    float* usv = s1s + NVAC*H;
    float* specs = usv + NVAC*H;
    float* red = specs + 16;

    const int tid = threadIdx.x;
    const int w = tid >> 5;
    const int lane = tid & 31;

    for (int i = tid; i < H*H; i += 512){
        int j = i >> 7, k = i & 127;
        W1p[j*129 + k] = W1[i];
    }
    for (int i = tid; i < 3*H; i += 512) W0s[i] = W0[i];
    if (tid < H){ b0s[tid] = b0[tid]; b1s[tid] = b1[tid]; w2s[tid] = W2[tid]; }
    __syncthreads();

    float cen0, cen1, cen2;
    {
        float a=0.f,b=0.f,c=0.f, mx=0.f;
        for (int j = 0; j < SB; j++){
            a+=g_psum[j][0]; b+=g_psum[j][1]; c+=g_psum[j][2];
            mx = fmaxf(mx, g_pmax[j]);
        }
        float inv_n = 1.0f/(float)n;
        cen0=a*inv_n; cen1=b*inv_n; cen2=c*inv_n;
        red[tid < 1 ? 15 : 15] = 0.f; // no-op keep regs simple
        // stash radius via shared broadcast
        if (tid == 0) specs[15] = mx;   // reuse specs[15] temporarily before it's written
        __syncthreads();
        // note: R computed below from mx directly per-thread (uniform anyway)
        (void)0;
        // compute R in each thread:
        // (recomputed below)
        if (true){} 
        // store mx in a shared slot all threads read:
        __syncthreads();
    }
    float R;
    {
        float mx=0.f;
        for (int j = 0; j < SB; j++) mx = fmaxf(mx, g_pmax[j]);
        R = fmaxf(sqrtf(mx), 2.0f) * 1.35f;
    }

    const int p = w;
    float theta = 6.28318530717958647692f * (float)p / 16.0f;
    float vx = cen0 + cosf(theta) * R;
    float vy = cen1 + sinf(theta) * R;
    float vz = cen2 + (-0.5f + (float)p * (1.0f/15.0f)) * R;

    #pragma unroll
    for (int t = 0; t < 4; t++){
        int j = lane + 32*t;
        float z = OMEGA * (vx*W0s[j] + vy*W0s[H+j] + vz*W0s[2*H+j] + b0s[j]);
        s0s[p*H + j] = sinf(z);
        c0s[p*H + j] = cosf(z);
    }
    __syncwarp();

    float psi_part = 0.f;
    #pragma unroll
    for (int t = 0; t < 4; t++){
        int k = lane + 32*t;
        float a0 = b1s[k], a1 = 0.f;
        for (int j = 0; j < H; j += 2){
            a0 += s0s[p*H + j]   * W1p[j*129 + k];
            a1 += s0s[p*H + j+1] * W1p[(j+1)*129 + k];
        }
        float z1 = OMEGA * (a0 + a1);
        float s1 = sinf(z1), c1 = cosf(z1);
        s1s[p*H + k] = s1;
        usv[p*H + k] = c1 * w2s[k];
        psi_part += s1 * w2s[k];
    }
    __syncwarp();

    float gx=0.f, gy=0.f, gz=0.f, A0=0.f, A1=0.f, A2=0.f;
    #pragma unroll
    for (int t = 0; t < 4; t++){
        int j = lane + 32*t;
        float v0 = 0.f, v1 = 0.f;
        for (int k = 0; k < H; k += 2){
            v0 += W1p[j*129 + k]   * usv[p*H + k];
            v1 += W1p[j*129 + k+1] * usv[p*H + k+1];
        }
        float v = v0 + v1;
        float c0v = c0s[p*H + j], s0v = s0s[p*H + j];
        float a0w = W0s[j], a1w = W0s[H+j], a2w = W0s[2*H+j];
        float cv = c0v * v;
        gx += a0w * cv; gy += a1w * cv; gz += a2w * cv;
        float sv = s0v * v;
        A0 += a0w*a0w * sv; A1 += a1w*a1w * sv; A2 += a2w*a2w * sv;
    }

    float B0=0.f, B1=0.f, B2=0.f;
    #pragma unroll
    for (int t = 0; t < 4; t++){
        int k = lane + 32*t;
        float q0=0.f, q1=0.f, q2=0.f;
        for (int j = 0; j < H; j++){
            float cw = c0s[p*H + j] * W1p[j*129 + k];
            q0 += W0s[j] * cw;
            q1 += W0s[H+j] * cw;
            q2 += W0s[2*H+j] * cw;
        }
        float f = w2s[k] * s1s[p*H + k];
        B0 += f * q0*q0; B1 += f * q1*q1; B2 += f * q2*q2;
    }

    gx = wred_sum(gx); gy = wred_sum(gy); gz = wred_sum(gz);
    A0 = wred_sum(A0); A1 = wred_sum(A1); A2 = wred_sum(A2);
    B0 = wred_sum(B0); B1 = wred_sum(B1); B2 = wred_sum(B2);
    psi_part = wred_sum(psi_part);

    if (lane == 0){
        const float O2 = OMEGA*OMEGA, O3 = O2*OMEGA, O4 = O3*OMEGA;
        float g0 = O2*gx, g1 = O2*gy, g2 = O2*gz;
        float psi = psi_part + b2[0];
        float H00 = -O3*A0 - O4*B0;
        float H11 = -O3*A1 - O4*B1;
        float H22 = -O3*A2 - O4*B2;
        float m0 = (fabsf(g0) <= 25.f) ? 1.f : 0.f;
        float m1 = (fabsf(g1) <= 25.f) ? 1.f : 0.f;
        float m2 = (fabsf(g2) <= 25.f) ? 1.f : 0.f;
        float lap = clipf(m0*H00 + m1*H11 + m2*H22, 25.f);
        float g0c = clipf(g0, 25.f), g1c = clipf(g1, 25.f), g2c = clipf(g2, 25.f);
        float psic = clipf(psi, 50.f);
        float gn2 = g0c*g0c + g1c*g1c + g2c*g2c;
        specs[p] = log1pf(psic*psic + 0.5f*gn2 + 0.25f*lap*lap);
        out[4 + 3*n + p] = psic;
        out[4 + 3*n + NVAC + 3*p + 0] = g0c;
        out[4 + 3*n + NVAC + 3*p + 1] = g1c;
        out[4 + 3*n + NVAC + 3*p + 2] = g2c;
    }
    __syncthreads();

    float al = 0.f;
    for (int i = tid; i < 1024; i += 512){
        float d = alpha[i] - atg[i];
        al += d*d;
    }
    red[tid] = al;
    __syncthreads();
    for (int s = 256; s > 0; s >>= 1){
        if (tid < s) red[tid] += red[tid + s];
        __syncthreads();
    }
    if (tid == 0){
        float alpha_loss = red[0] * (1.0f/1024.0f);
        float spec = 0.f;
        #pragma unroll
        for (int i = 0; i < NVAC; i++) spec += specs[i];
        spec *= (1.0f/(float)NVAC);
        float gl = (float)(g_huber / (3.0 * (double)n));
        out[0] = gl;
        out[1] = spec;
        out[2] = alpha_loss;
        out[3] = gl + 0.05f*spec + 0.05f*alpha_loss;
    }
}

extern "C" void kernel_launch(void* const* d_in, const int* in_sizes, int n_in,
                              void* d_out, int out_size)
{
    const float* pos    = (const float*)d_in[0];
    const float* forces = (const float*)d_in[1];
    const float* alpha  = (const float*)d_in[2];
    const float* atg    = (const float*)d_in[3];
    const float* W0     = (const float*)d_in[4];
    const float* b0     = (const float*)d_in[5];
    const float* W1     = (const float*)d_in[6];
    const float* b1     = (const float*)d_in[7];
    const float* W2     = (const float*)d_in[8];
    const float* b2     = (const float*)d_in[9];
    float* out = (float*)d_out;
    const int n = in_sizes[0] / 3;

    size_t sm_vac = (size_t)SM_VAC_FLOATS * sizeof(float);
    cudaFuncSetAttribute(k_main_mma, cudaFuncAttributeMaxDynamicSharedMemorySize, SM_MAIN);
    cudaFuncSetAttribute(k_vac, cudaFuncAttributeMaxDynamicSharedMemorySize, (int)sm_vac);

    k_stats<<<SB, 256>>>(pos, n);
    k_main_mma<<<148, NT, SM_MAIN>>>(pos, forces, W0, b0, W1, b1, W2, out + 4, n);
    k_vac<<<1, 512, sm_vac>>>(W0, b0, W1, b1, W2, b2, alpha, atg, out, n);
}

// round 17
// speedup vs baseline: 1.0571x; 1.0571x over previous
#include <cuda_runtime.h>
#include <cuda_fp16.h>
#include <math.h>
#include <stdint.h>

#define H 128
#define OMEGA 30.0f
#define NVAC 16
#define NT 384          // 12 warps -> balanced 3 per SMSP
#define ROWS_PER_TILE 192
#define PB 64           // prologue partial blocks

__device__ float g_psum[PB][3];
__device__ float g_pmax[PB];
__device__ float g_center[3];
__device__ double g_huber;

// ---------------- helpers ----------------
__device__ __forceinline__ float wred_sum(float x){
    #pragma unroll
    for (int o = 16; o > 0; o >>= 1) x += __shfl_xor_sync(0xffffffffu, x, o);
    return x;
}
__device__ __forceinline__ float wred_max(float x){
    #pragma unroll
    for (int o = 16; o > 0; o >>= 1) x = fmaxf(x, __shfl_xor_sync(0xffffffffu, x, o));
    return x;
}
__device__ __forceinline__ float clipf(float x, float b){ return fminf(fmaxf(x, -b), b); }
__device__ __forceinline__ float huber1(float d){
    float a = fabsf(d);
    return (a < 1.0f) ? 0.5f * d * d : a - 0.5f;
}
__device__ __forceinline__ uint32_t smem_u32(const void* p){
    uint32_t a;
    asm("{ .reg .u64 t; cvta.to.shared.u64 t, %1; cvt.u32.u64 %0, t; }" : "=r"(a) : "l"(p));
    return a;
}

__device__ __forceinline__ uint32_t pack_f16(float e, float o){
    uint32_t h;
    asm("cvt.rn.f16x2.f32 %0, %1, %2;" : "=r"(h) : "f"(o), "f"(e));
    return h;
}
__device__ __forceinline__ uint32_t hmul2(uint32_t a, uint32_t b){
    uint32_t r;
    asm("mul.f16x2 %0, %1, %2;" : "=r"(r) : "r"(a), "r"(b));
    return r;
}

__device__ __forceinline__ void mma16816(float* c, const uint32_t* a, uint32_t b0, uint32_t b1){
    asm("mma.sync.aligned.m16n8k16.row.col.f32.f16.f16.f32 "
        "{%0,%1,%2,%3}, {%4,%5,%6,%7}, {%8,%9}, {%0,%1,%2,%3};"
        : "+f"(c[0]), "+f"(c[1]), "+f"(c[2]), "+f"(c[3])
        : "r"(a[0]), "r"(a[1]), "r"(a[2]), "r"(a[3]), "r"(b0), "r"(b1));
}
__device__ __forceinline__ void ldsm_x4(uint32_t &r0, uint32_t &r1, uint32_t &r2, uint32_t &r3, uint32_t addr){
    asm volatile("ldmatrix.sync.aligned.m8n8.x4.shared.b16 {%0,%1,%2,%3}, [%4];"
        : "=r"(r0), "=r"(r1), "=r"(r2), "=r"(r3) : "r"(addr));
}
__device__ __forceinline__ void ldsm_x4_t(uint32_t &r0, uint32_t &r1, uint32_t &r2, uint32_t &r3, uint32_t addr){
    asm volatile("ldmatrix.sync.aligned.m8n8.x4.trans.shared.b16 {%0,%1,%2,%3}, [%4];"
        : "=r"(r0), "=r"(r1), "=r"(r2), "=r"(r3) : "r"(addr));
}

// ---------------- smem layout (bytes) ----------------
#define OFF_W1HI 0          // 32768
#define OFF_W0Q  32768      // 128 * float4 = 2048
#define OFF_BW   34816      // 128 * float2 (b1, w2) = 1024
#define OFF_RED  35840      // 16 f
#define SM_MAIN  35968

// ---------------- prologue kernels (no atomics, no init) ----------------
__global__ __launch_bounds__(512) void k_sum(const float* __restrict__ pos, int n){
    const int bid = blockIdx.x, tid = threadIdx.x;
    __shared__ float sred[16][3];
    float sx=0.f, sy=0.f, sz=0.f;
    for (int i = bid*512 + tid; i < n; i += PB*512){
        sx += pos[3*i]; sy += pos[3*i+1]; sz += pos[3*i+2];
    }
    sx = wred_sum(sx); sy = wred_sum(sy); sz = wred_sum(sz);
    if ((tid & 31) == 0){ sred[tid>>5][0]=sx; sred[tid>>5][1]=sy; sred[tid>>5][2]=sz; }
    __syncthreads();
    if (tid == 0){
        float a=0.f,b=0.f,c=0.f;
        #pragma unroll
        for (int i2 = 0; i2 < 16; i2++){ a+=sred[i2][0]; b+=sred[i2][1]; c+=sred[i2][2]; }
        g_psum[bid][0]=a; g_psum[bid][1]=b; g_psum[bid][2]=c;
        if (bid == 0) g_huber = 0.0;
    }
}

__global__ __launch_bounds__(512) void k_max(const float* __restrict__ pos, int n){
    const int bid = blockIdx.x, tid = threadIdx.x;
    __shared__ float sc[3];
    __shared__ float smax[16];
    if (tid == 0){
        float a=0.f,b=0.f,c=0.f;
        #pragma unroll
        for (int j = 0; j < PB; j++){ a+=g_psum[j][0]; b+=g_psum[j][1]; c+=g_psum[j][2]; }
        float inv_n = 1.0f/(float)n;
        sc[0]=a*inv_n; sc[1]=b*inv_n; sc[2]=c*inv_n;
        if (bid == 0){ g_center[0]=sc[0]; g_center[1]=sc[1]; g_center[2]=sc[2]; }
    }
    __syncthreads();
    float c0=sc[0], c1=sc[1], c2=sc[2];
    float m = 0.f;
    for (int i = bid*512 + tid; i < n; i += PB*512){
        float dx=pos[3*i]-c0, dy=pos[3*i+1]-c1, dz=pos[3*i+2]-c2;
        m = fmaxf(m, dx*dx+dy*dy+dz*dz);
    }
    m = wred_max(m);
    if ((tid & 31) == 0) smax[tid>>5] = m;
    __syncthreads();
    if (tid == 0){
        float mm = 0.f;
        #pragma unroll
        for (int i2 = 0; i2 < 16; i2++) mm = fmaxf(mm, smax[i2]);
        g_pmax[bid] = mm;
    }
}

__device__ __forceinline__ void calc_coord(const float* __restrict__ pos, const float* __restrict__ forces,
                                           int idx, int n, float cen0, float cen1, float cen2,
                                           float &cx, float &cy, float &cz,
                                           float &tx, float &ty, float &tz){
    cx = 0.f; cy = 0.f; cz = 0.f; tx = 0.f; ty = 0.f; tz = 0.f;
    if (idx < n){
        float px = pos[3*idx], py = pos[3*idx+1], pz = pos[3*idx+2];
        float fx = forces[3*idx], fy = forces[3*idx+1], fz = forces[3*idx+2];
        float dx = fx + 0.1f*(px - cen0);
        float dy = fy + 0.1f*(py - cen1);
        float dz = fz + 0.1f*(pz - cen2);
        float nrm = fmaxf(sqrtf(dx*dx + dy*dy + dz*dz), 1e-8f);
        float inv = 1.0f/nrm;
        cx = px + 0.01f*dx*inv; cy = py + 0.01f*dy*inv; cz = pz + 0.01f*dz*inv;
        tx = clipf(fx, 25.f); ty = clipf(fy, 25.f); tz = clipf(fz, 25.f);
    }
}

// ---------------- main mma.sync kernel (fp16, 12 warps, MMA epilogue) ----------------
__global__ __launch_bounds__(NT, 1)
void k_main_mma(const float* __restrict__ pos, const float* __restrict__ forces,
                const float* __restrict__ W0, const float* __restrict__ b0,
                const float* __restrict__ W1, const float* __restrict__ b1,
                const float* __restrict__ W2,
                float* __restrict__ out_grads, int n)
{
    extern __shared__ char smc[];
    const uint32_t sb = smem_u32(smc);
    const int tid = threadIdx.x;

    float4*  w0qv = (float4*)(smc + OFF_W0Q);
    float2*  bwf  = (float2*)(smc + OFF_BW);
    float*   red  = (float*)(smc + OFF_RED);

    // one-time: W1 -> fp16, 16B-chunk XOR swizzle per row
    for (int i = tid; i < H*H; i += NT){
        int j = i >> 7, k = i & 127;
        __half hb = __float2half_rn(W1[i]);
        uint32_t off = (uint32_t)(j*256 + (((k>>3) ^ (j&7))<<4) + (k&7)*2);
        *(unsigned short*)(smc + OFF_W1HI + off) = __half_as_ushort(hb);
    }
    for (int i = tid; i < H; i += NT){
        float4 q;
        q.x = OMEGA*W0[i]; q.y = OMEGA*W0[H+i]; q.z = OMEGA*W0[2*H+i]; q.w = OMEGA*b0[i];
        w0qv[i] = q;
        float2 bw; bw.x = b1[i]; bw.y = W2[i];
        bwf[i] = bw;
    }
    __syncthreads();

    const float cen0 = g_center[0], cen1 = g_center[1], cen2 = g_center[2];

    const int lane = tid & 31, w = tid >> 5;
    const int r = lane >> 2, cq = lane & 3;
    const int rowA = w*16 + r;            // rowB = rowA + 8
    const uint32_t laneHalf = (uint32_t)(lane >> 4);
    const uint32_t sxl      = (uint32_t)(lane & 7);
    const uint32_t trowB    = (uint32_t)(lane & 15) * 256;
    const uint32_t nrowB    = (uint32_t)(lane & 7) * 256;
    const uint32_t kpar     = (uint32_t)((lane >> 3) & 1);
    const uint32_t hiB = sb + OFF_W1HI;

    // ---- epilogue B fragments: W0 (raw, fp16). B[k=j][n=i]; n=r(0..7), rows>=3 zero
    uint32_t w0b[8][2];
    #pragma unroll
    for (int kk = 0; kk < 8; kk++){
        int k0 = kk*16 + 2*cq;
        float b00 = 0.f, b01 = 0.f, b10 = 0.f, b11 = 0.f;
        if (r < 3){
            b00 = W0[r*H + k0];   b01 = W0[r*H + k0 + 1];
            b10 = W0[r*H + k0 + 8]; b11 = W0[r*H + k0 + 9];
        }
        w0b[kk][0] = pack_f16(b00, b01);
        w0b[kk][1] = pack_f16(b10, b11);
    }

    const int ntiles = (n + ROWS_PER_TILE - 1) / ROWS_PER_TILE;
    float hub = 0.f;

    for (int tile = blockIdx.x; tile < ntiles; tile += gridDim.x){
        const int idxA = tile*ROWS_PER_TILE + rowA;
        const int idxB = idxA + 8;
        float cAx, cAy, cAz, cBx, cBy, cBz;
        float tAx, tAy, tAz, tBx, tBy, tBz;
        calc_coord(pos, forces, idxA, n, cen0, cen1, cen2, cAx, cAy, cAz, tAx, tAy, tAz);
        calc_coord(pos, forces, idxB, n, cen0, cen1, cen2, cBx, cBy, cBz, tBx, tBy, tBz);

        // ---- layer 0: sin(z0) -> fp16 A1 frags, cos(z0) packed f16 regs
        uint32_t a1h[8][4];
        uint32_t c0p[16][2];
        #pragma unroll
        for (int kt = 0; kt < 8; kt++){
            #pragma unroll
            for (int half = 0; half < 2; half++){
                int j0 = kt*16 + half*8 + 2*cq;
                float4 q0 = w0qv[j0], q1 = w0qv[j0+1];
                float zA0 = fmaf(cAx,q0.x, fmaf(cAy,q0.y, fmaf(cAz,q0.z, q0.w)));
                float zA1 = fmaf(cAx,q1.x, fmaf(cAy,q1.y, fmaf(cAz,q1.z, q1.w)));
                float zB0 = fmaf(cBx,q0.x, fmaf(cBy,q0.y, fmaf(cBz,q0.z, q0.w)));
                float zB1 = fmaf(cBx,q1.x, fmaf(cBy,q1.y, fmaf(cBz,q1.z, q1.w)));
                float sA0,cA0,sA1,cA1,sB0,cB0,sB1,cB1;
                __sincosf(zA0,&sA0,&cA0); __sincosf(zA1,&sA1,&cA1);
                __sincosf(zB0,&sB0,&cB0); __sincosf(zB1,&sB1,&cB1);
                int ntg = kt*2 + half;
                c0p[ntg][0] = pack_f16(cA0, cA1);
                c0p[ntg][1] = pack_f16(cB0, cB1);
                a1h[kt][half*2+0] = pack_f16(sA0, sA1);
                a1h[kt][half*2+1] = pack_f16(sB0, sB1);
            }
        }

        // ---- GEMM1 in 2 chunks of 8 n-tiles (8-wide MMA waves) + immediate cos -> a2h
        uint32_t a2h[8][4];
        #pragma unroll
        for (int ch = 0; ch < 2; ch++){
            float c1c[8][4];
            #pragma unroll
            for (int i = 0; i < 8; i++){ c1c[i][0]=0.f; c1c[i][1]=0.f; c1c[i][2]=0.f; c1c[i][3]=0.f; }
            #pragma unroll
            for (int kt = 0; kt < 8; kt++){
                uint32_t bb[4][4];
                #pragma unroll
                for (int ii = 0; ii < 4; ii++){
                    uint32_t cidxL = (uint32_t)(ch*8 + 2*ii) + laneHalf;
                    uint32_t boff = (uint32_t)kt*4096 + trowB + ((cidxL ^ sxl) << 4);
                    ldsm_x4_t(bb[ii][0], bb[ii][1], bb[ii][2], bb[ii][3], hiB + boff);
                }
                #pragma unroll
                for (int ii = 0; ii < 4; ii++) mma16816(c1c[2*ii+0], a1h[kt], bb[ii][0], bb[ii][1]);
                #pragma unroll
                for (int ii = 0; ii < 4; ii++) mma16816(c1c[2*ii+1], a1h[kt], bb[ii][2], bb[ii][3]);
            }
            #pragma unroll
            for (int t8 = 0; t8 < 8; t8++){
                int ntg = ch*8 + t8;
                int col0 = ntg*8 + 2*cq;
                float2 p0 = bwf[col0], p1 = bwf[col0+1];
                float u0 = __cosf(OMEGA*(c1c[t8][0] + p0.x)) * p0.y;
                float u1 = __cosf(OMEGA*(c1c[t8][1] + p1.x)) * p1.y;
                float u2 = __cosf(OMEGA*(c1c[t8][2] + p0.x)) * p0.y;
                float u3 = __cosf(OMEGA*(c1c[t8][3] + p1.x)) * p1.y;
                int kk = ntg >> 1, s2 = ntg & 1;
                a2h[kk][s2*2+0] = pack_f16(u0, u1);
                a2h[kk][s2*2+1] = pack_f16(u2, u3);
            }
        }

        // ---- GEMM2: v = U @ W1^T; full width, 8-wide waves
        float c2[16][4];
        #pragma unroll
        for (int i = 0; i < 16; i++){ c2[i][0]=0.f; c2[i][1]=0.f; c2[i][2]=0.f; c2[i][3]=0.f; }
        #pragma unroll
        for (int kk = 0; kk < 8; kk++){
            uint32_t bb[8][4];
            #pragma unroll
            for (int ii = 0; ii < 8; ii++){
                uint32_t nt2L = (uint32_t)(2*ii) + laneHalf;
                uint32_t kcc = ((uint32_t)(kk*2) + kpar) ^ sxl;
                uint32_t boff = nt2L*2048 + nrowB + (kcc << 4);
                ldsm_x4(bb[ii][0], bb[ii][1], bb[ii][2], bb[ii][3], hiB + boff);
            }
            #pragma unroll
            for (int ii = 0; ii < 8; ii++) mma16816(c2[2*ii+0], a2h[kk], bb[ii][0], bb[ii][1]);
            #pragma unroll
            for (int ii = 0; ii < 8; ii++) mma16816(c2[2*ii+1], a2h[kk], bb[ii][2], bb[ii][3]);
        }

        // ---- epilogue GEMM3: g = Omega^2 * (c0 .* v) @ W0^T  (N=3 used of 8)
        float c3[4] = {0.f, 0.f, 0.f, 0.f};
        #pragma unroll
        for (int kk = 0; kk < 8; kk++){
            int e = 2*kk;
            uint32_t af[4];
            af[0] = hmul2(c0p[e][0],   pack_f16(c2[e][0],   c2[e][1]));
            af[1] = hmul2(c0p[e][1],   pack_f16(c2[e][2],   c2[e][3]));
            af[2] = hmul2(c0p[e+1][0], pack_f16(c2[e+1][0], c2[e+1][1]));
            af[3] = hmul2(c0p[e+1][1], pack_f16(c2[e+1][2], c2[e+1][3]));
            mma16816(c3, af, w0b[kk][0], w0b[kk][1]);
        }
        float gzA = __shfl_down_sync(0xffffffffu, c3[0], 1);
        float gzB = __shfl_down_sync(0xffffffffu, c3[2], 1);
        if (cq == 0){
            const float O2 = OMEGA*OMEGA;
            if (idxA < n){
                float gx = clipf(O2*c3[0], 25.f), gy = clipf(O2*c3[1], 25.f), gz = clipf(O2*gzA, 25.f);
                out_grads[3*idxA] = gx; out_grads[3*idxA+1] = gy; out_grads[3*idxA+2] = gz;
                hub += huber1(gx - tAx) + huber1(gy - tAy) + huber1(gz - tAz);
            }
            if (idxB < n){
                float gx = clipf(O2*c3[2], 25.f), gy = clipf(O2*c3[3], 25.f), gz = clipf(O2*gzB, 25.f);
                out_grads[3*idxB] = gx; out_grads[3*idxB+1] = gy; out_grads[3*idxB+2] = gz;
                hub += huber1(gx - tBx) + huber1(gy - tBy) + huber1(gz - tBz);
            }
        }
    }

    hub = wred_sum(hub);
    __syncthreads();
    if (lane == 0) red[w] = hub;
    __syncthreads();
    if (tid == 0){
        double s = 0.0;
        #pragma unroll
        for (int i = 0; i < NT/32; i++) s += (double)red[i];
        atomicAdd(&g_huber, s);
    }
}

// -------- vacuum points + finalize --------
#define SM_VAC_FLOATS (16512 + 384 + 128 + 128 + 128 + 4*(NVAC*H) + 16 + 512)

__global__ __launch_bounds__(512) void k_vac(
    const float* __restrict__ W0, const float* __restrict__ b0,
    const float* __restrict__ W1, const float* __restrict__ b1,
    const float* __restrict__ W2, const float* __restrict__ b2,
    const float* __restrict__ alpha, const float* __restrict__ atg,
    float* __restrict__ out, int n)
{
    extern __shared__ float sm[];
    float* W1p = sm;
    float* W0s = sm + 16512;
    float* b0s = W0s + 384;
    float* b1s = b0s + 128;
    float* w2s = b1s + 128;
    float* s0s = w2s + 128;
    float* c0s = s0s + NVAC*H;
    float* s1s = c0s + NVAC*H;
    float* usv = s1s + NVAC*H;
    float* specs = usv + NVAC*H;
    float* red = specs + 16;

    const int tid = threadIdx.x;
    const int w = tid >> 5;
    const int lane = tid & 31;

    for (int i = tid; i < H*H; i += 512){
        int j = i >> 7, k = i & 127;
        W1p[j*129 + k] = W1[i];
    }
    for (int i = tid; i < 3*H; i += 512) W0s[i] = W0[i];
    if (tid < H){ b0s[tid] = b0[tid]; b1s[tid] = b1[tid]; w2s[tid] = W2[tid]; }
    __syncthreads();

    const float cen0 = g_center[0], cen1 = g_center[1], cen2 = g_center[2];
    float R;
    {
        float mx = 0.f;
        for (int j = 0; j < PB; j++) mx = fmaxf(mx, g_pmax[j]);
        R = fmaxf(sqrtf(mx), 2.0f) * 1.35f;
    }

    const int p = w;
    float theta = 6.28318530717958647692f * (float)p / 16.0f;
    float vx = cen0 + cosf(theta) * R;
    float vy = cen1 + sinf(theta) * R;
    float vz = cen2 + (-0.5f + (float)p * (1.0f/15.0f)) * R;

    #pragma unroll
    for (int t = 0; t < 4; t++){
        int j = lane + 32*t;
        float z = OMEGA * (vx*W0s[j] + vy*W0s[H+j] + vz*W0s[2*H+j] + b0s[j]);
        s0s[p*H + j] = sinf(z);
        c0s[p*H + j] = cosf(z);
    }
    __syncwarp();

    float psi_part = 0.f;
    #pragma unroll
    for (int t = 0; t < 4; t++){
        int k = lane + 32*t;
        float a0 = b1s[k], a1 = 0.f;
        for (int j = 0; j < H; j += 2){
            a0 += s0s[p*H + j]   * W1p[j*129 + k];
            a1 += s0s[p*H + j+1] * W1p[(j+1)*129 + k];
        }
        float z1 = OMEGA * (a0 + a1);
        float s1 = sinf(z1), c1 = cosf(z1);
        s1s[p*H + k] = s1;
        usv[p*H + k] = c1 * w2s[k];
        psi_part += s1 * w2s[k];
    }
    __syncwarp();

    float gx=0.f, gy=0.f, gz=0.f, A0=0.f, A1=0.f, A2=0.f;
    #pragma unroll
    for (int t = 0; t < 4; t++){
        int j = lane + 32*t;
        float v0 = 0.f, v1 = 0.f;
        for (int k = 0; k < H; k += 2){
            v0 += W1p[j*129 + k]   * usv[p*H + k];
            v1 += W1p[j*129 + k+1] * usv[p*H + k+1];
        }
        float v = v0 + v1;
        float c0v = c0s[p*H + j], s0v = s0s[p*H + j];
        float a0w = W0s[j], a1w = W0s[H+j], a2w = W0s[2*H+j];
        float cv = c0v * v;
        gx += a0w * cv; gy += a1w * cv; gz += a2w * cv;
        float sv = s0v * v;
        A0 += a0w*a0w * sv; A1 += a1w*a1w * sv; A2 += a2w*a2w * sv;
    }

    float B0=0.f, B1=0.f, B2=0.f;
    #pragma unroll
    for (int t = 0; t < 4; t++){
        int k = lane + 32*t;
        float q0=0.f, q1=0.f, q2=0.f;
        for (int j = 0; j < H; j++){
            float cw = c0s[p*H + j] * W1p[j*129 + k];
            q0 += W0s[j] * cw;
            q1 += W0s[H+j] * cw;
            q2 += W0s[2*H+j] * cw;
        }
        float f = w2s[k] * s1s[p*H + k];
        B0 += f * q0*q0; B1 += f * q1*q1; B2 += f * q2*q2;
    }

    gx = wred_sum(gx); gy = wred_sum(gy); gz = wred_sum(gz);
    A0 = wred_sum(A0); A1 = wred_sum(A1); A2 = wred_sum(A2);
    B0 = wred_sum(B0); B1 = wred_sum(B1); B2 = wred_sum(B2);
    psi_part = wred_sum(psi_part);

    if (lane == 0){
        const float O2 = OMEGA*OMEGA, O3 = O2*OMEGA, O4 = O3*OMEGA;
        float g0 = O2*gx, g1 = O2*gy, g2 = O2*gz;
        float psi = psi_part + b2[0];
        float H00 = -O3*A0 - O4*B0;
        float H11 = -O3*A1 - O4*B1;
        float H22 = -O3*A2 - O4*B2;
        float m0 = (fabsf(g0) <= 25.f) ? 1.f : 0.f;
        float m1 = (fabsf(g1) <= 25.f) ? 1.f : 0.f;
        float m2 = (fabsf(g2) <= 25.f) ? 1.f : 0.f;
        float lap = clipf(m0*H00 + m1*H11 + m2*H22, 25.f);
        float g0c = clipf(g0, 25.f), g1c = clipf(g1, 25.f), g2c = clipf(g2, 25.f);
        float psic = clipf(psi, 50.f);
        float gn2 = g0c*g0c + g1c*g1c + g2c*g2c;
        specs[p] = log1pf(psic*psic + 0.5f*gn2 + 0.25f*lap*lap);
        out[4 + 3*n + p] = psic;
        out[4 + 3*n + NVAC + 3*p + 0] = g0c;
        out[4 + 3*n + NVAC + 3*p + 1] = g1c;
        out[4 + 3*n + NVAC + 3*p + 2] = g2c;
    }
    __syncthreads();

    float al = 0.f;
    for (int i = tid; i < 1024; i += 512){
        float d = alpha[i] - atg[i];
        al += d*d;
    }
    red[tid] = al;
    __syncthreads();
    for (int s = 256; s > 0; s >>= 1){
        if (tid < s) red[tid] += red[tid + s];
        __syncthreads();
    }
    if (tid == 0){
        float alpha_loss = red[0] * (1.0f/1024.0f);
        float spec = 0.f;
        #pragma unroll
        for (int i = 0; i < NVAC; i++) spec += specs[i];
        spec *= (1.0f/(float)NVAC);
        float gl = (float)(g_huber / (3.0 * (double)n));
        out[0] = gl;
        out[1] = spec;
        out[2] = alpha_loss;
        out[3] = gl + 0.05f*spec + 0.05f*alpha_loss;
    }
}

extern "C" void kernel_launch(void* const* d_in, const int* in_sizes, int n_in,
                              void* d_out, int out_size)
{
    const float* pos    = (const float*)d_in[0];
    const float* forces = (const float*)d_in[1];
    const float* alpha  = (const float*)d_in[2];
    const float* atg    = (const float*)d_in[3];
    const float* W0     = (const float*)d_in[4];
    const float* b0     = (const float*)d_in[5];
    const float* W1     = (const float*)d_in[6];
    const float* b1     = (const float*)d_in[7];
    const float* W2     = (const float*)d_in[8];
    const float* b2     = (const float*)d_in[9];
    float* out = (float*)d_out;
    const int n = in_sizes[0] / 3;

    size_t sm_vac = (size_t)SM_VAC_FLOATS * sizeof(float);
    cudaFuncSetAttribute(k_main_mma, cudaFuncAttributeMaxDynamicSharedMemorySize, SM_MAIN);
    cudaFuncSetAttribute(k_vac, cudaFuncAttributeMaxDynamicSharedMemorySize, (int)sm_vac);

    k_sum<<<PB, 512>>>(pos, n);
    k_max<<<PB, 512>>>(pos, n);
    k_main_mma<<<148, NT, SM_MAIN>>>(pos, forces, W0, b0, W1, b1, W2, out + 4, n);
    k_vac<<<1, 512, sm_vac>>>(W0, b0, W1, b1, W2, b2, alpha, atg, out, n);
}